// round 6
// baseline (speedup 1.0000x reference)
#include <cuda_runtime.h>
#include <cuda_bf16.h>
#include <cstdint>

#define BATCH 128
#define TDIM  256
#define IND   1024
#define UD    1024
#define MTOT  (BATCH * TDIM)

#define BM    256                   // = TDIM: one CTA covers all t of one batch
#define BN    64
#define KP    8                     // k-pairs per stage (BK=16)
#define NIT   (IND / 16)            // 64 mainloop iters

#define LDWA  264                   // words per kp-row, A (256 + 8 pad)
#define LDWB  72                    // words per kp-row, B (64 + 8 pad)
#define LDH   72                    // htile row stride (words)

#define A_WORDS (KP * LDWA)         // 2112 per buffer
#define B_WORDS (KP * LDWB)         // 576 per buffer
#define AB_TOTAL (4 * A_WORDS + 4 * B_WORDS)      // 10752 words = 43008 B
#define SMEM_BYTES (BM * LDH * 4)                 // 73728 B (htile; superset)

// ---------------------------------------------------------------------------
__device__ __forceinline__ void mma16(float* c, const uint32_t* a, uint32_t b0, uint32_t b1) {
    asm volatile(
        "mma.sync.aligned.m16n8k16.row.col.f32.bf16.bf16.f32 "
        "{%0,%1,%2,%3}, {%4,%5,%6,%7}, {%8,%9}, {%0,%1,%2,%3};"
        : "+f"(c[0]), "+f"(c[1]), "+f"(c[2]), "+f"(c[3])
        : "r"(a[0]), "r"(a[1]), "r"(a[2]), "r"(a[3]), "r"(b0), "r"(b1));
}

// split two fp32 (consecutive k) -> packed bf16x2 hi word + lo word
__device__ __forceinline__ void pack_split(float a, float b, uint32_t& hw, uint32_t& lw) {
    __nv_bfloat162 h2 = __floats2bfloat162_rn(a, b);
    float2 hf = __bfloat1622float2(h2);
    __nv_bfloat162 l2 = __floats2bfloat162_rn(a - hf.x, b - hf.y);
    hw = *reinterpret_cast<uint32_t*>(&h2);
    lw = *reinterpret_cast<uint32_t*>(&l2);
}

__device__ __forceinline__ void sts128(uint32_t* base, int idx, const uint32_t* w) {
    *reinterpret_cast<uint4*>(base + idx) = make_uint4(w[0], w[1], w[2], w[3]);
}

// ---------------------------------------------------------------------------
// Fused GEMM + LIF scan.
//   h[t,u] = sum_k x[b,k,t] * W[k,u]   (3-pass bf16 split, fp32 accum)
//   then per-u scan over t, writing out[t, b, u] = sigmoid(v_t - 1).
// CTA: M=256 (all t of batch b) x N=64 u's. 8 warps, warp tile 32x64.
// ---------------------------------------------------------------------------
__global__ __launch_bounds__(256, 2)
void snn_fused_kernel(const float* __restrict__ x, const float* __restrict__ W,
                      float* __restrict__ out)
{
    extern __shared__ uint32_t S[];

    const int tid  = threadIdx.x;
    const int lane = tid & 31;
    const int wid  = tid >> 5;                 // warpM 0..7
    const int qid  = lane >> 2;                // 0..7
    const int qt   = lane & 3;                 // 0..3

    const int b  = blockIdx.y;                 // batch
    const int u0 = blockIdx.x * BN;

    // smem buffers: [stage][hi/lo]
    uint32_t* Ab[2][2];
    uint32_t* Bb[2][2];
    #pragma unroll
    for (int st = 0; st < 2; st++)
        #pragma unroll
        for (int hl = 0; hl < 2; hl++) {
            Ab[st][hl] = S + (st * 2 + hl) * A_WORDS;
            Bb[st][hl] = S + 4 * A_WORDS + (st * 2 + hl) * B_WORDS;
        }

    // ---- loader mappings ----
    // A: 256 threads cover 128 t-cols x 8 kp per pass; 2 passes (t +0, +128)
    const int lkp  = tid >> 5;                 // 0..7
    const int lcol = (tid & 31) * 4;           // t 0..124
    const float* xk = x + (size_t)b * IND * TDIM;          // + k*TDIM + t
    // B: threads 0..127 cover 64 u-cols x 8 kp
    const int bkp  = tid >> 4;                 // 0..15 (only <8 used via tid<128)
    const int bcol = (tid & 15) * 4;
    const float* wk = W + u0;                              // + k*UD + n

    float acc[2][8][4];
    #pragma unroll
    for (int mt = 0; mt < 2; mt++)
        #pragma unroll
        for (int nt = 0; nt < 8; nt++)
            #pragma unroll
            for (int j = 0; j < 4; j++)
                acc[mt][nt][j] = 0.0f;

    // ---- stage 0 load ----
    {
        uint32_t hw[4], lw[4];
        #pragma unroll
        for (int p = 0; p < 2; p++) {
            float4 e = *reinterpret_cast<const float4*>(xk + (size_t)(2 * lkp)     * TDIM + lcol + p * 128);
            float4 o = *reinterpret_cast<const float4*>(xk + (size_t)(2 * lkp + 1) * TDIM + lcol + p * 128);
            pack_split(e.x, o.x, hw[0], lw[0]); pack_split(e.y, o.y, hw[1], lw[1]);
            pack_split(e.z, o.z, hw[2], lw[2]); pack_split(e.w, o.w, hw[3], lw[3]);
            sts128(Ab[0][0], lkp * LDWA + lcol + p * 128, hw);
            sts128(Ab[0][1], lkp * LDWA + lcol + p * 128, lw);
        }
        if (tid < 128) {
            float4 e = *reinterpret_cast<const float4*>(wk + (size_t)(2 * bkp)     * UD + bcol);
            float4 o = *reinterpret_cast<const float4*>(wk + (size_t)(2 * bkp + 1) * UD + bcol);
            pack_split(e.x, o.x, hw[0], lw[0]); pack_split(e.y, o.y, hw[1], lw[1]);
            pack_split(e.z, o.z, hw[2], lw[2]); pack_split(e.w, o.w, hw[3], lw[3]);
            sts128(Bb[0][0], bkp * LDWB + bcol, hw);
            sts128(Bb[0][1], bkp * LDWB + bcol, lw);
        }
    }
    __syncthreads();

    const int mbase = wid * 32 + qid;

    for (int kt = 0; kt < NIT; kt++) {
        const int cb = kt & 1;

        // prefetch next stage globals
        float4 pae0, pao0, pae1, pao1, pbe, pbo;
        if (kt + 1 < NIT) {
            const int k0 = (kt + 1) * 16;
            pae0 = *reinterpret_cast<const float4*>(xk + (size_t)(k0 + 2 * lkp)     * TDIM + lcol);
            pao0 = *reinterpret_cast<const float4*>(xk + (size_t)(k0 + 2 * lkp + 1) * TDIM + lcol);
            pae1 = *reinterpret_cast<const float4*>(xk + (size_t)(k0 + 2 * lkp)     * TDIM + lcol + 128);
            pao1 = *reinterpret_cast<const float4*>(xk + (size_t)(k0 + 2 * lkp + 1) * TDIM + lcol + 128);
            if (tid < 128) {
                pbe = *reinterpret_cast<const float4*>(wk + (size_t)(k0 + 2 * bkp)     * UD + bcol);
                pbo = *reinterpret_cast<const float4*>(wk + (size_t)(k0 + 2 * bkp + 1) * UD + bcol);
            }
        }

        const uint32_t* Ah = Ab[cb][0];
        const uint32_t* Al = Ab[cb][1];
        const uint32_t* Bh = Bb[cb][0];
        const uint32_t* Bl = Bb[cb][1];

        uint32_t ahi[2][4], alo[2][4];
        #pragma unroll
        for (int mt = 0; mt < 2; mt++) {
            const int m = mbase + mt * 16;
            ahi[mt][0] = Ah[qt * LDWA + m];
            ahi[mt][1] = Ah[qt * LDWA + m + 8];
            ahi[mt][2] = Ah[(qt + 4) * LDWA + m];
            ahi[mt][3] = Ah[(qt + 4) * LDWA + m + 8];
            alo[mt][0] = Al[qt * LDWA + m];
            alo[mt][1] = Al[qt * LDWA + m + 8];
            alo[mt][2] = Al[(qt + 4) * LDWA + m];
            alo[mt][3] = Al[(qt + 4) * LDWA + m + 8];
        }

        #pragma unroll
        for (int nt = 0; nt < 8; nt++) {
            const int n = qid + nt * 8;
            const uint32_t bh0 = Bh[qt * LDWB + n];
            const uint32_t bh1 = Bh[(qt + 4) * LDWB + n];
            const uint32_t bl0 = Bl[qt * LDWB + n];
            const uint32_t bl1 = Bl[(qt + 4) * LDWB + n];
            #pragma unroll
            for (int mt = 0; mt < 2; mt++) {
                mma16(acc[mt][nt], ahi[mt], bh0, bh1);   // hi*hi
                mma16(acc[mt][nt], alo[mt], bh0, bh1);   // lo*hi
                mma16(acc[mt][nt], ahi[mt], bl0, bl1);   // hi*lo
            }
        }

        if (kt + 1 < NIT) {
            const int nb = cb ^ 1;
            uint32_t hw[4], lw[4];
            pack_split(pae0.x, pao0.x, hw[0], lw[0]); pack_split(pae0.y, pao0.y, hw[1], lw[1]);
            pack_split(pae0.z, pao0.z, hw[2], lw[2]); pack_split(pae0.w, pao0.w, hw[3], lw[3]);
            sts128(Ab[nb][0], lkp * LDWA + lcol, hw);
            sts128(Ab[nb][1], lkp * LDWA + lcol, lw);
            pack_split(pae1.x, pao1.x, hw[0], lw[0]); pack_split(pae1.y, pao1.y, hw[1], lw[1]);
            pack_split(pae1.z, pao1.z, hw[2], lw[2]); pack_split(pae1.w, pao1.w, hw[3], lw[3]);
            sts128(Ab[nb][0], lkp * LDWA + lcol + 128, hw);
            sts128(Ab[nb][1], lkp * LDWA + lcol + 128, lw);
            if (tid < 128) {
                pack_split(pbe.x, pbo.x, hw[0], lw[0]); pack_split(pbe.y, pbo.y, hw[1], lw[1]);
                pack_split(pbe.z, pbo.z, hw[2], lw[2]); pack_split(pbe.w, pbo.w, hw[3], lw[3]);
                sts128(Bb[nb][0], bkp * LDWB + bcol, hw);
                sts128(Bb[nb][1], bkp * LDWB + bcol, lw);
            }
        }
        __syncthreads();
    }

    // ---- epilogue 1: acc -> smem htile[t][u] (fp32, row stride LDH) ----
    float* H = reinterpret_cast<float*>(S);
    #pragma unroll
    for (int mt = 0; mt < 2; mt++) {
        const int row = wid * 32 + mt * 16 + qid;
        #pragma unroll
        for (int nt = 0; nt < 8; nt++) {
            const int col = nt * 8 + 2 * qt;
            *reinterpret_cast<float2*>(H + (size_t)row * LDH + col) =
                make_float2(acc[mt][nt][0], acc[mt][nt][1]);
            *reinterpret_cast<float2*>(H + (size_t)(row + 8) * LDH + col) =
                make_float2(acc[mt][nt][2], acc[mt][nt][3]);
        }
    }
    __syncthreads();

    // ---- epilogue 2: per-u LIF scan over t (64 threads) ----
    if (tid < BN) {
        const float* Hc = H + tid;
        float* op = out + (size_t)b * UD + u0 + tid;

        float v = 0.0f, syn = 0.0f;
        float hv = Hc[0];
        #pragma unroll 4
        for (int t = 0; t < TDIM; t++) {
            const float hn = (t + 1 < TDIM) ? Hc[(size_t)(t + 1) * LDH] : 0.0f;
            const float s  = 1.0f / (1.0f + __expf(1.0f - v));
            const float vn = (0.85f * v + syn) * (1.0f - s);
            syn = 0.9f * syn + hv;
            v   = vn;
            op[(size_t)t * (BATCH * UD)] = s;
            hv = hn;
        }
    }
}

// ---------------------------------------------------------------------------
extern "C" void kernel_launch(void* const* d_in, const int* in_sizes, int n_in,
                              void* d_out, int out_size)
{
    const float* x = (const float*)d_in[0];   // [128, 1024, 256]
    const float* W = (const float*)d_in[1];   // [1024, 1024]
    float* out = (float*)d_out;               // [256, 128, 1024]

    static bool attr_set = false;
    if (!attr_set) {
        cudaFuncSetAttribute(snn_fused_kernel,
                             cudaFuncAttributeMaxDynamicSharedMemorySize, SMEM_BYTES);
        attr_set = true;
    }

    dim3 grid(UD / BN, BATCH);                // (16, 128): x-fastest -> A reuse in L2
    snn_fused_kernel<<<grid, 256, SMEM_BYTES>>>(x, W, out);
}

// round 7
// speedup vs baseline: 1.1307x; 1.1307x over previous
#include <cuda_runtime.h>
#include <cuda_bf16.h>
#include <cstdint>

#define BATCH 128
#define TDIM  256
#define IND   1024
#define UD    1024

#define BM    256                   // = TDIM: one CTA covers all t of one batch
#define BN    64
#define KP    8                     // k-pairs per stage (BK=16)
#define KPTOT (IND / 2)             // 512 k-pairs total
#define NIT   (IND / 16)            // 64 mainloop iters

#define LDWA  264                   // words per kp-row, A smem (256 + 8 pad)
#define LDWB  72                    // words per kp-row, B smem (64 + 8 pad)
#define LDH   72                    // htile row stride (fp32 words)

#define A_WORDS (KP * LDWA)         // 2112 words per (stage, hi/lo)
#define B_WORDS (KP * LDWB)         // 576
#define SMEM_BYTES (BM * LDH * 4)   // 73728 B (htile; superset of mainloop bufs)

// ---------------------------------------------------------------------------
// Pre-split packed operands (word = bf16x2 of k-even/k-odd), __device__ scratch
// ---------------------------------------------------------------------------
__device__ uint32_t g_ahi[(size_t)BATCH * KPTOT * TDIM];   // 64 MB [b][kp][t]
__device__ uint32_t g_alo[(size_t)BATCH * KPTOT * TDIM];   // 64 MB
__device__ uint32_t g_bhi[(size_t)KPTOT * UD];             // 2 MB  [kp][u]
__device__ uint32_t g_blo[(size_t)KPTOT * UD];             // 2 MB

// ---------------------------------------------------------------------------
__device__ __forceinline__ void mma16(float* c, const uint32_t* a, uint32_t b0, uint32_t b1) {
    asm volatile(
        "mma.sync.aligned.m16n8k16.row.col.f32.bf16.bf16.f32 "
        "{%0,%1,%2,%3}, {%4,%5,%6,%7}, {%8,%9}, {%0,%1,%2,%3};"
        : "+f"(c[0]), "+f"(c[1]), "+f"(c[2]), "+f"(c[3])
        : "r"(a[0]), "r"(a[1]), "r"(a[2]), "r"(a[3]), "r"(b0), "r"(b1));
}

__device__ __forceinline__ void pack_split(float a, float b, uint32_t& hw, uint32_t& lw) {
    __nv_bfloat162 h2 = __floats2bfloat162_rn(a, b);
    float2 hf = __bfloat1622float2(h2);
    __nv_bfloat162 l2 = __floats2bfloat162_rn(a - hf.x, b - hf.y);
    hw = *reinterpret_cast<uint32_t*>(&h2);
    lw = *reinterpret_cast<uint32_t*>(&l2);
}

__device__ __forceinline__ uint32_t smem_u32(const void* p) {
    uint32_t a;
    asm("{ .reg .u64 t; cvta.to.shared.u64 t, %1; cvt.u32.u64 %0, t; }" : "=r"(a) : "l"(p));
    return a;
}
__device__ __forceinline__ void cp16(uint32_t sdst, const uint32_t* gsrc) {
    asm volatile("cp.async.cg.shared.global [%0], [%1], 16;" :: "r"(sdst), "l"(gsrc));
}
#define CP_COMMIT() asm volatile("cp.async.commit_group;" ::: "memory")
#define CP_WAIT1()  asm volatile("cp.async.wait_group 1;" ::: "memory")
#define CP_WAIT0()  asm volatile("cp.async.wait_group 0;" ::: "memory")

// ---------------------------------------------------------------------------
// Split kernels: fp32 -> packed bf16 hi/lo pair words, layout matching smem.
// ---------------------------------------------------------------------------
__global__ __launch_bounds__(256)
void split_x_kernel(const float* __restrict__ x)
{
    const int idx = blockIdx.x * 256 + threadIdx.x;    // b(7) | kp(9) | t4(6)
    const int t4 = (idx & 63) * 4;
    const int kp = (idx >> 6) & (KPTOT - 1);
    const int b  = idx >> 15;

    const float* xp = x + ((size_t)b * IND + 2 * kp) * TDIM + t4;
    float4 e = *reinterpret_cast<const float4*>(xp);
    float4 o = *reinterpret_cast<const float4*>(xp + TDIM);

    uint32_t hw[4], lw[4];
    pack_split(e.x, o.x, hw[0], lw[0]); pack_split(e.y, o.y, hw[1], lw[1]);
    pack_split(e.z, o.z, hw[2], lw[2]); pack_split(e.w, o.w, hw[3], lw[3]);

    const size_t off = ((size_t)b * KPTOT + kp) * TDIM + t4;
    *reinterpret_cast<uint4*>(g_ahi + off) = make_uint4(hw[0], hw[1], hw[2], hw[3]);
    *reinterpret_cast<uint4*>(g_alo + off) = make_uint4(lw[0], lw[1], lw[2], lw[3]);
}

__global__ __launch_bounds__(256)
void split_w_kernel(const float* __restrict__ W)
{
    const int idx = blockIdx.x * 256 + threadIdx.x;    // kp(9) | u4(8)
    const int u4 = (idx & 255) * 4;
    const int kp = idx >> 8;

    const float* wp = W + (size_t)(2 * kp) * UD + u4;
    float4 e = *reinterpret_cast<const float4*>(wp);
    float4 o = *reinterpret_cast<const float4*>(wp + UD);

    uint32_t hw[4], lw[4];
    pack_split(e.x, o.x, hw[0], lw[0]); pack_split(e.y, o.y, hw[1], lw[1]);
    pack_split(e.z, o.z, hw[2], lw[2]); pack_split(e.w, o.w, hw[3], lw[3]);

    const size_t off = (size_t)kp * UD + u4;
    *reinterpret_cast<uint4*>(g_bhi + off) = make_uint4(hw[0], hw[1], hw[2], hw[3]);
    *reinterpret_cast<uint4*>(g_blo + off) = make_uint4(lw[0], lw[1], lw[2], lw[3]);
}

// ---------------------------------------------------------------------------
// Fused GEMM + LIF scan. CTA: M=256 (all t of batch b) x N=64.
// cp.async double-buffered mainloop (no data regs, no in-loop cvt).
// ---------------------------------------------------------------------------
__global__ __launch_bounds__(256, 2)
void snn_fused_kernel(float* __restrict__ out)
{
    extern __shared__ uint32_t S[];

    const int tid  = threadIdx.x;
    const int lane = tid & 31;
    const int wid  = tid >> 5;                 // warpM 0..7
    const int qid  = lane >> 2;
    const int qt   = lane & 3;

    const int b  = blockIdx.y;
    const int u0 = blockIdx.x * BN;

    uint32_t* Ab[2][2];
    uint32_t* Bb[2][2];
    #pragma unroll
    for (int st = 0; st < 2; st++)
        #pragma unroll
        for (int hl = 0; hl < 2; hl++) {
            Ab[st][hl] = S + (st * 2 + hl) * A_WORDS;
            Bb[st][hl] = S + 4 * A_WORDS + (st * 2 + hl) * B_WORDS;
        }

    // ---- cp.async addressing ----
    // A: 512 16B-chunks per (stage,hi/lo); thread does rows r0=tid>>6 and r0+4
    const int ar0 = tid >> 6;                  // 0..3
    const int acw = (tid & 63) * 4;            // word col
    const uint32_t* gah = g_ahi + (size_t)b * KPTOT * TDIM;
    const uint32_t* gal = g_alo + (size_t)b * KPTOT * TDIM;
    // B: 128 chunks hi (tid<128) / lo (tid>=128)
    const int br  = (tid & 127) >> 4;          // 0..7
    const int bcw = ((tid & 127) & 15) * 4;
    const uint32_t* gb = (tid < 128) ? g_bhi : g_blo;

    uint32_t aDst0[2], aDst1[2], bDst;         // smem dst (u32) per stage
    #pragma unroll
    for (int st = 0; st < 2; st++) {
        aDst0[st] = smem_u32(Ab[st][0] + ar0 * LDWA + acw);          // hi rows r0, r0+4 via +4*LDWA
        aDst1[st] = smem_u32(Ab[st][1] + ar0 * LDWA + acw);
    }
    bDst = smem_u32(((tid < 128) ? Bb[0][0] : Bb[0][1]) + br * LDWB + bcw);
    const uint32_t bStageStep = (uint32_t)(2 * B_WORDS * 4);         // stage0->1 bytes

    auto issue_stage = [&](int kt, int st) {
        const size_t akBase = (size_t)(kt * KP) * TDIM;
        cp16(aDst0[st],                 gah + akBase + (size_t)ar0 * TDIM + acw);
        cp16(aDst0[st] + 4 * LDWA * 4,  gah + akBase + (size_t)(ar0 + 4) * TDIM + acw);
        cp16(aDst1[st],                 gal + akBase + (size_t)ar0 * TDIM + acw);
        cp16(aDst1[st] + 4 * LDWA * 4,  gal + akBase + (size_t)(ar0 + 4) * TDIM + acw);
        cp16(bDst + (uint32_t)st * bStageStep,
             gb + (size_t)(kt * KP + br) * UD + u0 + bcw);
    };

    float acc[2][8][4];
    #pragma unroll
    for (int mt = 0; mt < 2; mt++)
        #pragma unroll
        for (int nt = 0; nt < 8; nt++)
            #pragma unroll
            for (int j = 0; j < 4; j++)
                acc[mt][nt][j] = 0.0f;

    // prologue: stages 0,1 in flight
    issue_stage(0, 0); CP_COMMIT();
    issue_stage(1, 1); CP_COMMIT();
    CP_WAIT1();                    // stage 0 resident
    __syncthreads();

    const int mbase = wid * 32 + qid;

    for (int kt = 0; kt < NIT; kt++) {
        const int cb = kt & 1;
        const uint32_t* Ah = Ab[cb][0];
        const uint32_t* Al = Ab[cb][1];
        const uint32_t* Bh = Bb[cb][0];
        const uint32_t* Bl = Bb[cb][1];

        uint32_t ahi[2][4], alo[2][4];
        #pragma unroll
        for (int mt = 0; mt < 2; mt++) {
            const int m = mbase + mt * 16;
            ahi[mt][0] = Ah[qt * LDWA + m];
            ahi[mt][1] = Ah[qt * LDWA + m + 8];
            ahi[mt][2] = Ah[(qt + 4) * LDWA + m];
            ahi[mt][3] = Ah[(qt + 4) * LDWA + m + 8];
            alo[mt][0] = Al[qt * LDWA + m];
            alo[mt][1] = Al[qt * LDWA + m + 8];
            alo[mt][2] = Al[(qt + 4) * LDWA + m];
            alo[mt][3] = Al[(qt + 4) * LDWA + m + 8];
        }

        #pragma unroll
        for (int nt = 0; nt < 8; nt++) {
            const int n = qid + nt * 8;
            const uint32_t bh0 = Bh[qt * LDWB + n];
            const uint32_t bh1 = Bh[(qt + 4) * LDWB + n];
            const uint32_t bl0 = Bl[qt * LDWB + n];
            const uint32_t bl1 = Bl[(qt + 4) * LDWB + n];
            #pragma unroll
            for (int mt = 0; mt < 2; mt++) {
                mma16(acc[mt][nt], ahi[mt], bh0, bh1);   // hi*hi
                mma16(acc[mt][nt], alo[mt], bh0, bh1);   // lo*hi
                mma16(acc[mt][nt], ahi[mt], bl0, bl1);   // hi*lo
            }
        }

        __syncthreads();                       // all warps done reading buf cb
        if (kt + 2 < NIT) {
            issue_stage(kt + 2, cb); CP_COMMIT();
            CP_WAIT1();                        // stage kt+1 resident
        } else {
            CP_WAIT0();
        }
        __syncthreads();                       // stage kt+1 visible to all
    }

    // ---- epilogue 1: acc -> smem htile[t][u] ----
    float* H = reinterpret_cast<float*>(S);
    #pragma unroll
    for (int mt = 0; mt < 2; mt++) {
        const int row = wid * 32 + mt * 16 + qid;
        #pragma unroll
        for (int nt = 0; nt < 8; nt++) {
            const int col = nt * 8 + 2 * qt;
            *reinterpret_cast<float2*>(H + (size_t)row * LDH + col) =
                make_float2(acc[mt][nt][0], acc[mt][nt][1]);
            *reinterpret_cast<float2*>(H + (size_t)(row + 8) * LDH + col) =
                make_float2(acc[mt][nt][2], acc[mt][nt][3]);
        }
    }
    __syncthreads();

    // ---- epilogue 2: per-u LIF scan over t (64 threads) ----
    if (tid < BN) {
        const float* Hc = H + tid;
        float* op = out + (size_t)b * UD + u0 + tid;

        float v = 0.0f, syn = 0.0f;
        float hv = Hc[0];
        #pragma unroll 4
        for (int t = 0; t < TDIM; t++) {
            const float hn = (t + 1 < TDIM) ? Hc[(size_t)(t + 1) * LDH] : 0.0f;
            const float s  = 1.0f / (1.0f + __expf(1.0f - v));
            const float vn = (0.85f * v + syn) * (1.0f - s);
            syn = 0.9f * syn + hv;
            v   = vn;
            op[(size_t)t * (BATCH * UD)] = s;
            hv = hn;
        }
    }
}

// ---------------------------------------------------------------------------
extern "C" void kernel_launch(void* const* d_in, const int* in_sizes, int n_in,
                              void* d_out, int out_size)
{
    const float* x = (const float*)d_in[0];   // [128, 1024, 256]
    const float* W = (const float*)d_in[1];   // [1024, 1024]
    float* out = (float*)d_out;               // [256, 128, 1024]

    static bool attr_set = false;
    if (!attr_set) {
        cudaFuncSetAttribute(snn_fused_kernel,
                             cudaFuncAttributeMaxDynamicSharedMemorySize, SMEM_BYTES);
        attr_set = true;
    }

    split_x_kernel<<<(BATCH * KPTOT * (TDIM / 4)) / 256, 256>>>(x);
    split_w_kernel<<<(KPTOT * (UD / 4)) / 256, 256>>>(W);

    dim3 grid(UD / BN, BATCH);                // (16, 128)
    snn_fused_kernel<<<grid, 256, SMEM_BYTES>>>(out);
}